// round 8
// baseline (speedup 1.0000x reference)
#include <cuda_runtime.h>
#include <cuda_bf16.h>
#include <cstdint>

// Problem: B=4,S=4096 -> T=16384 tokens; IN_F=OUT_F=4096; G=32; GS=GO=128.
// y[t, g*128+n] = sum_k x[t, perm[g*128+k]] * W[g,n,k] + b[g,n]
#define IN_F   4096
#define G      32
#define TMAX   16384
#define TILE_T 128

// ---------------- device scratch (static; no allocation) ----------------
__device__ int      g_perm[IN_F];
__device__ uint32_t g_whf[64 * 4096];     // W hi fragments per half-group
__device__ uint32_t g_wlf[64 * 4096];     // W lo fragments
// Pre-swizzled A tiles: [ttile=128][g=32][32KB tile], hi and lo.
__device__ unsigned char g_xht[(size_t)128 * 32 * 32768];
__device__ unsigned char g_xlt[(size_t)128 * 32 * 32768];

__device__ __forceinline__ uint32_t smem_u32(const void* p) {
    uint32_t a;
    asm("{ .reg .u64 t; cvta.to.shared.u64 t, %1; cvt.u32.u64 %0, t; }" : "=r"(a) : "l"(p));
    return a;
}

__device__ __forceinline__ void split_pack(float v0, float v1, uint32_t& hp, uint32_t& lp) {
    __nv_bfloat16 h0 = __float2bfloat16(v0), h1 = __float2bfloat16(v1);
    __nv_bfloat16 l0 = __float2bfloat16(v0 - __bfloat162float(h0));
    __nv_bfloat16 l1 = __float2bfloat16(v1 - __bfloat162float(h1));
    hp = ((uint32_t)__bfloat16_as_ushort(h1) << 16) | __bfloat16_as_ushort(h0);
    lp = ((uint32_t)__bfloat16_as_ushort(l1) << 16) | __bfloat16_as_ushort(l0);
}

// ---------------- pass 0a: normalize perm (int64-or-int32 -> int32) ----------------
__global__ void convert_perm_kernel(const int* __restrict__ p32) {
    __shared__ int is64;
    if (threadIdx.x == 0) {
        int all0 = 1;
        #pragma unroll
        for (int i = 1; i < 16; i += 2) all0 &= (p32[i] == 0);
        is64 = all0;
    }
    __syncthreads();
    const int w = is64;
    for (int i = threadIdx.x; i < IN_F; i += blockDim.x)
        g_perm[i] = w ? p32[2 * i] : p32[i];
}

// ---------------- pass 0b: W -> split bf16, gmem-LDG fragment order ----------------
// e = (((wn*8 + ks)*32 + lane)*4 + nt)*2 + r
//   n  = (hg&1)*64 + wn*32 + nt*8 + lane/4 ; k0 = ks*16 + 2*(lane&3) + r*8
__global__ void wprep_kernel(const float* __restrict__ W) {
    const int hg = blockIdx.x;            // 0..63
    const int g = hg >> 1;
    for (int e = threadIdx.x; e < 4096; e += blockDim.x) {
        const int r    = e & 1;
        const int nt   = (e >> 1) & 3;
        const int lane = (e >> 3) & 31;
        const int ks   = (e >> 8) & 7;
        const int wn   = e >> 11;
        const int n    = (hg & 1) * 64 + wn * 32 + nt * 8 + (lane >> 2);
        const int k0   = ks * 16 + 2 * (lane & 3) + r * 8;
        const float v0 = W[((size_t)g * 128 + n) * 128 + k0];
        const float v1 = W[((size_t)g * 128 + n) * 128 + k0 + 1];
        uint32_t hp, lp; split_pack(v0, v1, hp, lp);
        g_whf[hg * 4096 + e] = hp;
        g_wlf[hg * 4096 + e] = lp;
    }
}

// ---------------- pass 1: permute + split + swizzle into GEMM-ready tiles ----------------
// Block: 4 tokens, 256 threads (8 warps). Warp task = (token pair, group).
// Half-warp (16 lanes) covers one token row: lane q handles kp=4q..4q+3 ->
// 8 smem gathers, 4 split_packs, ONE STG.128 per buffer (row fully coalesced).
__global__ __launch_bounds__(256) void xprep_kernel(const float* __restrict__ x) {
    extern __shared__ float rows[];                 // 4 * 4096 floats = 64 KB
    const int t0    = blockIdx.x * 4;
    const int ttile = t0 >> 7;
    const int tbase = t0 & 127;
    const int tid = threadIdx.x, lane = tid & 31, wid = tid >> 5;

    const float4* src = (const float4*)(x + (size_t)t0 * IN_F);
    for (int i = tid; i < 4096; i += 256) ((float4*)rows)[i] = src[i];
    __syncthreads();

    const int q   = lane & 15;                      // 16B chunk within row
    const int sub = lane >> 4;                      // token within pair

    #pragma unroll
    for (int i = 0; i < 8; ++i) {
        const int task = i * 8 + wid;               // 0..63
        const int tp   = task >> 5;                 // token pair 0..1
        const int g    = task & 31;
        const int tok  = tp * 2 + sub;              // 0..3
        const float* row = rows + tok * IN_F;
        const uint32_t t = (uint32_t)(tbase + tok);

        uint4 hv, lv;
        uint32_t* hw = (uint32_t*)&hv;
        uint32_t* lw = (uint32_t*)&lv;
        #pragma unroll
        for (int j = 0; j < 4; ++j) {
            const int kp = 4 * q + j;
            const int f0 = g_perm[g * 128 + 2 * kp];
            const int f1 = g_perm[g * 128 + 2 * kp + 1];
            split_pack(row[f0], row[f1], hw[j], lw[j]);
        }
        const uint32_t off = t * 256 + (((uint32_t)q ^ (t & 7)) << 4);
        const size_t tb = ((size_t)ttile * 32 + g) * 32768;
        *(uint4*)(g_xht + tb + off) = hv;
        *(uint4*)(g_xlt + tb + off) = lv;
    }
}

// ---------------- pass 2: HMMA block-diagonal GEMM ----------------
// CTA: 128 tokens x 128 outputs (FULL group), 256 threads (8 warps), warp
// grid 2(m) x 4(n), warp tile 64x32. A tile (hi/lo, 64 KB) loaded ONCE via
// cp.async and shared by all 8 warps -> 3 CTA/SM, 24 warps/SM.
// B straight from gmem (fragment-ordered, L1/L2-hot).
#define SM_AH 0
#define SM_AL 32768
#define SM_SZ 65536

__global__ __launch_bounds__(256, 3)
void bdl_mma_kernel(const float* __restrict__ bias, float* __restrict__ out)
{
    extern __shared__ char smem[];
    const uint32_t sb = smem_u32(smem);
    const int g  = blockIdx.x;
    const int t0 = blockIdx.y * TILE_T;
    const int tid = threadIdx.x, lane = tid & 31, wid = tid >> 5;

    // --- A: bulk cp.async of pre-swizzled hi/lo tiles (64 KB total) ---
    {
        const unsigned char* sh = g_xht + ((size_t)blockIdx.y * 32 + g) * 32768;
        const unsigned char* sl = g_xlt + ((size_t)blockIdx.y * 32 + g) * 32768;
        #pragma unroll 4
        for (int e = tid; e < 2048; e += 256) {
            asm volatile("cp.async.cg.shared.global [%0], [%1], 16;"
                         :: "r"(sb + SM_AH + e * 16), "l"(sh + e * 16));
            asm volatile("cp.async.cg.shared.global [%0], [%1], 16;"
                         :: "r"(sb + SM_AL + e * 16), "l"(sl + e * 16));
        }
        asm volatile("cp.async.commit_group;");
        asm volatile("cp.async.wait_group 0;");
    }
    __syncthreads();

    // --- mainloop: warp grid 2(m) x 4(n); warp tile 64 tokens x 32 outputs ---
    const int wm = wid & 1;         // rows [wm*64, wm*64+64)
    const int wn = wid >> 1;        // cols [wn*32, wn*32+32)
    const int hg  = g * 2 + (wn >> 1);
    const int wnn = wn & 1;

    const uint4* bhp = (const uint4*)(g_whf + hg * 4096 + wnn * 2048);
    const uint4* blp = (const uint4*)(g_wlf + hg * 4096 + wnn * 2048);

    float acc[4][4][4];
    #pragma unroll
    for (int mt = 0; mt < 4; ++mt)
        #pragma unroll
        for (int nt = 0; nt < 4; ++nt)
            #pragma unroll
            for (int q = 0; q < 4; ++q) acc[mt][nt][q] = 0.0f;

    #pragma unroll
    for (int ks = 0; ks < 8; ++ks) {
        const int bidx = (ks * 32 + lane) * 2;
        const uint4 h01 = __ldg(&bhp[bidx]);
        const uint4 h23 = __ldg(&bhp[bidx + 1]);
        const uint4 l01 = __ldg(&blp[bidx]);
        const uint4 l23 = __ldg(&blp[bidx + 1]);
        const uint32_t bh[4][2] = {{h01.x,h01.y},{h01.z,h01.w},{h23.x,h23.y},{h23.z,h23.w}};
        const uint32_t bl[4][2] = {{l01.x,l01.y},{l01.z,l01.w},{l23.x,l23.y},{l23.z,l23.w}};

        uint32_t ah[4][4], al[4][4];
        #pragma unroll
        for (int mt = 0; mt < 4; ++mt) {
            const uint32_t row = (uint32_t)(wm * 64 + mt * 16 + (lane & 15));
            const uint32_t c   = (uint32_t)(2 * ks + (lane >> 4));
            const uint32_t aoff = row * 256 + ((c ^ (row & 7)) << 4);
            asm volatile("ldmatrix.sync.aligned.m8n8.x4.shared.b16 {%0,%1,%2,%3}, [%4];"
                         : "=r"(ah[mt][0]), "=r"(ah[mt][1]), "=r"(ah[mt][2]), "=r"(ah[mt][3])
                         : "r"(sb + SM_AH + aoff));
            asm volatile("ldmatrix.sync.aligned.m8n8.x4.shared.b16 {%0,%1,%2,%3}, [%4];"
                         : "=r"(al[mt][0]), "=r"(al[mt][1]), "=r"(al[mt][2]), "=r"(al[mt][3])
                         : "r"(sb + SM_AL + aoff));
        }
        #pragma unroll
        for (int mt = 0; mt < 4; ++mt)
            #pragma unroll
            for (int nt = 0; nt < 4; ++nt) {
                asm volatile(
                    "mma.sync.aligned.m16n8k16.row.col.f32.bf16.bf16.f32 "
                    "{%0,%1,%2,%3}, {%4,%5,%6,%7}, {%8,%9}, {%0,%1,%2,%3};"
                    : "+f"(acc[mt][nt][0]), "+f"(acc[mt][nt][1]),
                      "+f"(acc[mt][nt][2]), "+f"(acc[mt][nt][3])
                    : "r"(ah[mt][0]), "r"(ah[mt][1]), "r"(ah[mt][2]), "r"(ah[mt][3]),
                      "r"(bh[nt][0]), "r"(bh[nt][1]));
                asm volatile(
                    "mma.sync.aligned.m16n8k16.row.col.f32.bf16.bf16.f32 "
                    "{%0,%1,%2,%3}, {%4,%5,%6,%7}, {%8,%9}, {%0,%1,%2,%3};"
                    : "+f"(acc[mt][nt][0]), "+f"(acc[mt][nt][1]),
                      "+f"(acc[mt][nt][2]), "+f"(acc[mt][nt][3])
                    : "r"(ah[mt][0]), "r"(ah[mt][1]), "r"(ah[mt][2]), "r"(ah[mt][3]),
                      "r"(bl[nt][0]), "r"(bl[nt][1]));
                asm volatile(
                    "mma.sync.aligned.m16n8k16.row.col.f32.bf16.bf16.f32 "
                    "{%0,%1,%2,%3}, {%4,%5,%6,%7}, {%8,%9}, {%0,%1,%2,%3};"
                    : "+f"(acc[mt][nt][0]), "+f"(acc[mt][nt][1]),
                      "+f"(acc[mt][nt][2]), "+f"(acc[mt][nt][3])
                    : "r"(al[mt][0]), "r"(al[mt][1]), "r"(al[mt][2]), "r"(al[mt][3]),
                      "r"(bh[nt][0]), "r"(bh[nt][1]));
            }
    }

    // --- epilogue: bias + st.v2 (c-fragment layout) ---
    const int colbase = g * 128 + wn * 32;
    #pragma unroll
    for (int nt = 0; nt < 4; ++nt) {
        const int col = colbase + nt * 8 + 2 * (lane & 3);
        const float b0 = bias[col], b1 = bias[col + 1];
        #pragma unroll
        for (int mt = 0; mt < 4; ++mt) {
            const int r0 = t0 + wm * 64 + mt * 16 + (lane >> 2);
            float2 v0 = make_float2(acc[mt][nt][0] + b0, acc[mt][nt][1] + b1);
            float2 v1 = make_float2(acc[mt][nt][2] + b0, acc[mt][nt][3] + b1);
            *(float2*)(out + (size_t)r0 * IN_F + col)       = v0;
            *(float2*)(out + (size_t)(r0 + 8) * IN_F + col) = v1;
        }
    }
}

// ---------------- launch ----------------
extern "C" void kernel_launch(void* const* d_in, const int* in_sizes, int n_in,
                              void* d_out, int out_size)
{
    const float* x    = (const float*)d_in[0];
    const int*   perm = (const int*)d_in[1];
    const float* W    = (const float*)d_in[2];
    const float* bias = (const float*)d_in[3];
    float* out = (float*)d_out;

    const int T = in_sizes[0] / IN_F;   // 16384

    convert_perm_kernel<<<1, 1024>>>(perm);
    wprep_kernel<<<64, 256>>>(W);

    cudaFuncSetAttribute(xprep_kernel,
                         cudaFuncAttributeMaxDynamicSharedMemorySize, 65536);
    xprep_kernel<<<T / 4, 256, 65536>>>(x);

    cudaFuncSetAttribute(bdl_mma_kernel,
                         cudaFuncAttributeMaxDynamicSharedMemorySize, SM_SZ);
    dim3 grid(G, T / TILE_T);           // (32, 128)
    bdl_mma_kernel<<<grid, 256, SM_SZ>>>(bias, out);
}

// round 9
// speedup vs baseline: 1.3041x; 1.3041x over previous
#include <cuda_runtime.h>
#include <cuda_bf16.h>
#include <cstdint>

// Problem: B=4,S=4096 -> T=16384 tokens; IN_F=OUT_F=4096; G=32; GS=GO=128.
// y[t, g*128+n] = sum_k x[t, perm[g*128+k]] * W[g,n,k] + b[g,n]
#define IN_F   4096
#define G      32
#define TMAX   16384
#define TILE_T 128

// ---------------- device scratch (static; no allocation) ----------------
__device__ int      g_perm[IN_F];
__device__ uint32_t g_whf[64 * 4096];     // W hi fragments per half-group
__device__ uint32_t g_wlf[64 * 4096];     // W lo fragments
// Pre-swizzled A tiles: [ttile=128][g=32][32KB tile], hi and lo.
__device__ unsigned char g_xht[(size_t)128 * 32 * 32768];
__device__ unsigned char g_xlt[(size_t)128 * 32 * 32768];

__device__ __forceinline__ uint32_t smem_u32(const void* p) {
    uint32_t a;
    asm("{ .reg .u64 t; cvta.to.shared.u64 t, %1; cvt.u32.u64 %0, t; }" : "=r"(a) : "l"(p));
    return a;
}

__device__ __forceinline__ void split_pack(float v0, float v1, uint32_t& hp, uint32_t& lp) {
    __nv_bfloat16 h0 = __float2bfloat16(v0), h1 = __float2bfloat16(v1);
    __nv_bfloat16 l0 = __float2bfloat16(v0 - __bfloat162float(h0));
    __nv_bfloat16 l1 = __float2bfloat16(v1 - __bfloat162float(h1));
    hp = ((uint32_t)__bfloat16_as_ushort(h1) << 16) | __bfloat16_as_ushort(h0);
    lp = ((uint32_t)__bfloat16_as_ushort(l1) << 16) | __bfloat16_as_ushort(l0);
}

// ---------------- pass 0a: normalize perm (int64-or-int32 -> int32) ----------------
__global__ void convert_perm_kernel(const int* __restrict__ p32) {
    __shared__ int is64;
    if (threadIdx.x == 0) {
        int all0 = 1;
        #pragma unroll
        for (int i = 1; i < 16; i += 2) all0 &= (p32[i] == 0);
        is64 = all0;
    }
    __syncthreads();
    const int w = is64;
    for (int i = threadIdx.x; i < IN_F; i += blockDim.x)
        g_perm[i] = w ? p32[2 * i] : p32[i];
}

// ---------------- pass 0b: W -> split bf16, gmem-LDG fragment order ----------------
// e = (((wn*8 + ks)*32 + lane)*4 + nt)*2 + r
//   n  = (hg&1)*64 + wn*32 + nt*8 + lane/4 ; k0 = ks*16 + 2*(lane&3) + r*8
__global__ void wprep_kernel(const float* __restrict__ W) {
    const int hg = blockIdx.x;            // 0..63
    const int g = hg >> 1;
    for (int e = threadIdx.x; e < 4096; e += blockDim.x) {
        const int r    = e & 1;
        const int nt   = (e >> 1) & 3;
        const int lane = (e >> 3) & 31;
        const int ks   = (e >> 8) & 7;
        const int wn   = e >> 11;
        const int n    = (hg & 1) * 64 + wn * 32 + nt * 8 + (lane >> 2);
        const int k0   = ks * 16 + 2 * (lane & 3) + r * 8;
        const float v0 = W[((size_t)g * 128 + n) * 128 + k0];
        const float v1 = W[((size_t)g * 128 + n) * 128 + k0 + 1];
        uint32_t hp, lp; split_pack(v0, v1, hp, lp);
        g_whf[hg * 4096 + e] = hp;
        g_wlf[hg * 4096 + e] = lp;
    }
}

// ---------------- pass 1: permute + split + swizzle into GEMM-ready tiles ----------------
// Block: 4 tokens, 256 threads (8 warps). Warp-task = (token pair, group):
// half-warp (16 lanes) covers one token row; lane q handles kp=4q..4q+3:
//   2x LDG.128 (perm int4), 8 LDS gathers, 4 split_packs, 2x STG.128.
__global__ __launch_bounds__(256) void xprep_kernel(const float* __restrict__ x) {
    extern __shared__ float rows[];                 // 4 * 4096 floats = 64 KB
    const int t0    = blockIdx.x * 4;
    const int ttile = t0 >> 7;
    const int tbase = t0 & 127;
    const int tid = threadIdx.x, lane = tid & 31, wid = tid >> 5;

    const float4* src = (const float4*)(x + (size_t)t0 * IN_F);
    for (int i = tid; i < 4096; i += 256) ((float4*)rows)[i] = src[i];
    __syncthreads();

    const int q   = lane & 15;                      // 16B chunk within row
    const int sub = lane >> 4;                      // token within pair

    #pragma unroll
    for (int i = 0; i < 8; ++i) {
        const int task = i * 8 + wid;               // 0..63
        const int tp   = task >> 5;                 // token pair 0..1
        const int g    = task & 31;
        const int tok  = tp * 2 + sub;              // 0..3
        const float* row = rows + tok * IN_F;
        const uint32_t t = (uint32_t)(tbase + tok);

        // perm indices for kp=4q..4q+3: 8 consecutive ints = two int4
        const int4* pp = (const int4*)(g_perm + g * 128 + 8 * q);
        const int4 pa = pp[0];
        const int4 pb = pp[1];

        uint4 hv, lv;
        split_pack(row[pa.x], row[pa.y], hv.x, lv.x);
        split_pack(row[pa.z], row[pa.w], hv.y, lv.y);
        split_pack(row[pb.x], row[pb.y], hv.z, lv.z);
        split_pack(row[pb.z], row[pb.w], hv.w, lv.w);

        const uint32_t off = t * 256 + (((uint32_t)q ^ (t & 7)) << 4);
        const size_t tb = ((size_t)ttile * 32 + g) * 32768;
        *(uint4*)(g_xht + tb + off) = hv;
        *(uint4*)(g_xlt + tb + off) = lv;
    }
}

// ---------------- pass 2: HMMA block-diagonal GEMM (R7 config) ----------------
// CTA: 128 tokens x 64 outputs (half-group), 128 threads, warp grid 2x2,
// warp tile 64x32. A tiles pre-swizzled via cp.async (64 KB smem -> 3 CTA/SM,
// 170-reg budget). B straight from gmem (fragment-ordered, L1/L2-hot).
#define SM_AH 0
#define SM_AL 32768
#define SM_SZ 65536

__global__ __launch_bounds__(128, 3)
void bdl_mma_kernel(const float* __restrict__ bias, float* __restrict__ out)
{
    extern __shared__ char smem[];
    const uint32_t sb = smem_u32(smem);
    const int hg = blockIdx.x;
    const int g  = hg >> 1;
    const int t0 = blockIdx.y * TILE_T;
    const int tid = threadIdx.x, lane = tid & 31, wid = tid >> 5;

    // --- A: bulk cp.async of pre-swizzled hi/lo tiles (64 KB) ---
    {
        const unsigned char* sh = g_xht + ((size_t)blockIdx.y * 32 + g) * 32768;
        const unsigned char* sl = g_xlt + ((size_t)blockIdx.y * 32 + g) * 32768;
        #pragma unroll 4
        for (int e = tid; e < 2048; e += 128) {
            asm volatile("cp.async.cg.shared.global [%0], [%1], 16;"
                         :: "r"(sb + SM_AH + e * 16), "l"(sh + e * 16));
            asm volatile("cp.async.cg.shared.global [%0], [%1], 16;"
                         :: "r"(sb + SM_AL + e * 16), "l"(sl + e * 16));
        }
        asm volatile("cp.async.commit_group;");
        asm volatile("cp.async.wait_group 0;");
    }
    __syncthreads();

    // --- mainloop: warp grid 2(m) x 2(n); warp tile 64 tokens x 32 outputs ---
    const int wm = wid & 1;
    const int wn = wid >> 1;

    const uint4* bhp = (const uint4*)(g_whf + hg * 4096 + wn * 2048);
    const uint4* blp = (const uint4*)(g_wlf + hg * 4096 + wn * 2048);

    float acc[4][4][4];
    #pragma unroll
    for (int mt = 0; mt < 4; ++mt)
        #pragma unroll
        for (int nt = 0; nt < 4; ++nt)
            #pragma unroll
            for (int q = 0; q < 4; ++q) acc[mt][nt][q] = 0.0f;

    #pragma unroll
    for (int ks = 0; ks < 8; ++ks) {
        const int bidx = (ks * 32 + lane) * 2;
        const uint4 h01 = __ldg(&bhp[bidx]);
        const uint4 h23 = __ldg(&bhp[bidx + 1]);
        const uint4 l01 = __ldg(&blp[bidx]);
        const uint4 l23 = __ldg(&blp[bidx + 1]);
        const uint32_t bh[4][2] = {{h01.x,h01.y},{h01.z,h01.w},{h23.x,h23.y},{h23.z,h23.w}};
        const uint32_t bl[4][2] = {{l01.x,l01.y},{l01.z,l01.w},{l23.x,l23.y},{l23.z,l23.w}};

        uint32_t ah[4][4], al[4][4];
        #pragma unroll
        for (int mt = 0; mt < 4; ++mt) {
            const uint32_t row = (uint32_t)(wm * 64 + mt * 16 + (lane & 15));
            const uint32_t c   = (uint32_t)(2 * ks + (lane >> 4));
            const uint32_t aoff = row * 256 + ((c ^ (row & 7)) << 4);
            asm volatile("ldmatrix.sync.aligned.m8n8.x4.shared.b16 {%0,%1,%2,%3}, [%4];"
                         : "=r"(ah[mt][0]), "=r"(ah[mt][1]), "=r"(ah[mt][2]), "=r"(ah[mt][3])
                         : "r"(sb + SM_AH + aoff));
            asm volatile("ldmatrix.sync.aligned.m8n8.x4.shared.b16 {%0,%1,%2,%3}, [%4];"
                         : "=r"(al[mt][0]), "=r"(al[mt][1]), "=r"(al[mt][2]), "=r"(al[mt][3])
                         : "r"(sb + SM_AL + aoff));
        }
        #pragma unroll
        for (int mt = 0; mt < 4; ++mt)
            #pragma unroll
            for (int nt = 0; nt < 4; ++nt) {
                asm volatile(
                    "mma.sync.aligned.m16n8k16.row.col.f32.bf16.bf16.f32 "
                    "{%0,%1,%2,%3}, {%4,%5,%6,%7}, {%8,%9}, {%0,%1,%2,%3};"
                    : "+f"(acc[mt][nt][0]), "+f"(acc[mt][nt][1]),
                      "+f"(acc[mt][nt][2]), "+f"(acc[mt][nt][3])
                    : "r"(ah[mt][0]), "r"(ah[mt][1]), "r"(ah[mt][2]), "r"(ah[mt][3]),
                      "r"(bh[nt][0]), "r"(bh[nt][1]));
                asm volatile(
                    "mma.sync.aligned.m16n8k16.row.col.f32.bf16.bf16.f32 "
                    "{%0,%1,%2,%3}, {%4,%5,%6,%7}, {%8,%9}, {%0,%1,%2,%3};"
                    : "+f"(acc[mt][nt][0]), "+f"(acc[mt][nt][1]),
                      "+f"(acc[mt][nt][2]), "+f"(acc[mt][nt][3])
                    : "r"(ah[mt][0]), "r"(ah[mt][1]), "r"(ah[mt][2]), "r"(ah[mt][3]),
                      "r"(bl[nt][0]), "r"(bl[nt][1]));
                asm volatile(
                    "mma.sync.aligned.m16n8k16.row.col.f32.bf16.bf16.f32 "
                    "{%0,%1,%2,%3}, {%4,%5,%6,%7}, {%8,%9}, {%0,%1,%2,%3};"
                    : "+f"(acc[mt][nt][0]), "+f"(acc[mt][nt][1]),
                      "+f"(acc[mt][nt][2]), "+f"(acc[mt][nt][3])
                    : "r"(al[mt][0]), "r"(al[mt][1]), "r"(al[mt][2]), "r"(al[mt][3]),
                      "r"(bh[nt][0]), "r"(bh[nt][1]));
            }
    }

    // --- epilogue: bias + st.v2 (c-fragment layout) ---
    const int colbase = g * 128 + (hg & 1) * 64 + wn * 32;
    #pragma unroll
    for (int nt = 0; nt < 4; ++nt) {
        const int col = colbase + nt * 8 + 2 * (lane & 3);
        const float b0 = bias[col], b1 = bias[col + 1];
        #pragma unroll
        for (int mt = 0; mt < 4; ++mt) {
            const int r0 = t0 + wm * 64 + mt * 16 + (lane >> 2);
            float2 v0 = make_float2(acc[mt][nt][0] + b0, acc[mt][nt][1] + b1);
            float2 v1 = make_float2(acc[mt][nt][2] + b0, acc[mt][nt][3] + b1);
            *(float2*)(out + (size_t)r0 * IN_F + col)       = v0;
            *(float2*)(out + (size_t)(r0 + 8) * IN_F + col) = v1;
        }
    }
}

// ---------------- launch ----------------
extern "C" void kernel_launch(void* const* d_in, const int* in_sizes, int n_in,
                              void* d_out, int out_size)
{
    const float* x    = (const float*)d_in[0];
    const int*   perm = (const int*)d_in[1];
    const float* W    = (const float*)d_in[2];
    const float* bias = (const float*)d_in[3];
    float* out = (float*)d_out;

    const int T = in_sizes[0] / IN_F;   // 16384

    convert_perm_kernel<<<1, 1024>>>(perm);
    wprep_kernel<<<64, 256>>>(W);

    cudaFuncSetAttribute(xprep_kernel,
                         cudaFuncAttributeMaxDynamicSharedMemorySize, 65536);
    xprep_kernel<<<T / 4, 256, 65536>>>(x);

    cudaFuncSetAttribute(bdl_mma_kernel,
                         cudaFuncAttributeMaxDynamicSharedMemorySize, SM_SZ);
    dim3 grid(64, T / TILE_T);          // (64 half-groups, 128 token tiles)
    bdl_mma_kernel<<<grid, 128, SM_SZ>>>(bias, out);
}

// round 10
// speedup vs baseline: 1.5419x; 1.1824x over previous
#include <cuda_runtime.h>
#include <cuda_fp16.h>
#include <cstdint>

// Problem: B=4,S=4096 -> T=16384 tokens; IN_F=OUT_F=4096; G=32; GS=GO=128.
// y[t, g*128+n] = sum_k x[t, perm[g*128+k]] * W[g,n,k] + b[g,n]
// Numerics: x -> fp16 (err ~2^-12), W -> fp16 hi + fp16 lo (err ~2^-24),
//           y = xh*Wh + xh*Wl with f32 accum  => norm rel err ~1.5e-4 < 1e-3.
#define IN_F   4096
#define G      32
#define TMAX   16384
#define TILE_T 128

// ---------------- device scratch (static; no allocation) ----------------
__device__ int      g_perm[IN_F];
__device__ uint32_t g_whf[64 * 4096];     // W hi fragments per half-group (fp16x2)
__device__ uint32_t g_wlf[64 * 4096];     // W lo fragments (fp16x2)
// Pre-swizzled fp16 A tiles: [ttile=128][g=32][32KB tile]
__device__ unsigned char g_xt[(size_t)128 * 32 * 32768];

__device__ __forceinline__ uint32_t smem_u32(const void* p) {
    uint32_t a;
    asm("{ .reg .u64 t; cvta.to.shared.u64 t, %1; cvt.u32.u64 %0, t; }" : "=r"(a) : "l"(p));
    return a;
}

__device__ __forceinline__ uint32_t pack_h2(float lo, float hi) {
    __half2 h = __floats2half2_rn(lo, hi);   // lo -> low 16 bits
    return *(uint32_t*)&h;
}

// ---------------- pass 0a: normalize perm (int64-or-int32 -> int32) ----------------
__global__ void convert_perm_kernel(const int* __restrict__ p32) {
    __shared__ int is64;
    if (threadIdx.x == 0) {
        int all0 = 1;
        #pragma unroll
        for (int i = 1; i < 16; i += 2) all0 &= (p32[i] == 0);
        is64 = all0;
    }
    __syncthreads();
    const int w = is64;
    for (int i = threadIdx.x; i < IN_F; i += blockDim.x)
        g_perm[i] = w ? p32[2 * i] : p32[i];
}

// ---------------- pass 0b: W -> fp16 hi/lo, gmem-LDG fragment order ----------------
// e = (((wn*8 + ks)*32 + lane)*4 + nt)*2 + r
//   n  = (hg&1)*64 + wn*32 + nt*8 + lane/4 ; k0 = ks*16 + 2*(lane&3) + r*8
__global__ void wprep_kernel(const float* __restrict__ W) {
    const int hg = blockIdx.x;            // 0..63
    const int g = hg >> 1;
    for (int e = threadIdx.x; e < 4096; e += blockDim.x) {
        const int r    = e & 1;
        const int nt   = (e >> 1) & 3;
        const int lane = (e >> 3) & 31;
        const int ks   = (e >> 8) & 7;
        const int wn   = e >> 11;
        const int n    = (hg & 1) * 64 + wn * 32 + nt * 8 + (lane >> 2);
        const int k0   = ks * 16 + 2 * (lane & 3) + r * 8;
        const float v0 = W[((size_t)g * 128 + n) * 128 + k0];
        const float v1 = W[((size_t)g * 128 + n) * 128 + k0 + 1];
        const float h0 = __half2float(__float2half_rn(v0));
        const float h1 = __half2float(__float2half_rn(v1));
        g_whf[hg * 4096 + e] = pack_h2(h0, h1);
        g_wlf[hg * 4096 + e] = pack_h2(v0 - h0, v1 - h1);
    }
}

// ---------------- pass 1: permute + fp16 convert into GEMM-ready tiles ----------------
// Block: 4 tokens, 256 threads (8 warps). Warp-task = (token pair, group):
// half-warp (16 lanes) covers one token row; lane q handles k=8q..8q+7:
//   2x LDG.128 (perm int4, L1-hot), 8 LDS gathers, 4 cvt, 1x STG.128.
__global__ __launch_bounds__(256) void xprep_kernel(const float* __restrict__ x) {
    extern __shared__ float rows[];                 // 4 * 4096 floats = 64 KB
    const int t0    = blockIdx.x * 4;
    const int ttile = t0 >> 7;
    const int tbase = t0 & 127;
    const int tid = threadIdx.x, lane = tid & 31, wid = tid >> 5;

    const float4* src = (const float4*)(x + (size_t)t0 * IN_F);
    for (int i = tid; i < 4096; i += 256) ((float4*)rows)[i] = src[i];
    __syncthreads();

    const int q   = lane & 15;                      // 16B chunk within row
    const int sub = lane >> 4;                      // token within pair

    #pragma unroll
    for (int i = 0; i < 8; ++i) {
        const int task = i * 8 + wid;               // 0..63
        const int tp   = task >> 5;                 // token pair 0..1
        const int g    = task & 31;
        const int tok  = tp * 2 + sub;              // 0..3
        const float* row = rows + tok * IN_F;
        const uint32_t t = (uint32_t)(tbase + tok);

        const int4* pp = (const int4*)(g_perm + g * 128 + 8 * q);
        const int4 pa = pp[0];
        const int4 pb = pp[1];

        uint4 v;
        v.x = pack_h2(row[pa.x], row[pa.y]);
        v.y = pack_h2(row[pa.z], row[pa.w]);
        v.z = pack_h2(row[pb.x], row[pb.y]);
        v.w = pack_h2(row[pb.z], row[pb.w]);

        const uint32_t off = t * 256 + (((uint32_t)q ^ (t & 7)) << 4);
        *(uint4*)(g_xt + ((size_t)ttile * 32 + g) * 32768 + off) = v;
    }
}

// ---------------- pass 2: HMMA block-diagonal GEMM ----------------
// CTA: 128 tokens x 64 outputs (half-group), 128 threads, warp grid 2x2,
// warp tile 64x32. A tile (fp16, 32 KB) via cp.async; 3 CTA/SM (170-reg cap).
// B (W hi/lo) straight from gmem (fragment-ordered, L1/L2-hot).
// Per (mt,nt): acc += ah*bh + ah*bl  (2 MMAs, f32 accum).
#define SM_SZ 32768

__global__ __launch_bounds__(128, 3)
void bdl_mma_kernel(const float* __restrict__ bias, float* __restrict__ out)
{
    extern __shared__ char smem[];
    const uint32_t sb = smem_u32(smem);
    const int hg = blockIdx.x;
    const int g  = hg >> 1;
    const int t0 = blockIdx.y * TILE_T;
    const int tid = threadIdx.x, lane = tid & 31, wid = tid >> 5;

    // --- A: bulk cp.async of pre-swizzled fp16 tile (32 KB) ---
    {
        const unsigned char* sa = g_xt + ((size_t)blockIdx.y * 32 + g) * 32768;
        #pragma unroll 4
        for (int e = tid; e < 2048; e += 128) {
            asm volatile("cp.async.cg.shared.global [%0], [%1], 16;"
                         :: "r"(sb + e * 16), "l"(sa + e * 16));
        }
        asm volatile("cp.async.commit_group;");
        asm volatile("cp.async.wait_group 0;");
    }
    __syncthreads();

    // --- mainloop: warp grid 2(m) x 2(n); warp tile 64 tokens x 32 outputs ---
    const int wm = wid & 1;
    const int wn = wid >> 1;

    const uint4* bhp = (const uint4*)(g_whf + hg * 4096 + wn * 2048);
    const uint4* blp = (const uint4*)(g_wlf + hg * 4096 + wn * 2048);

    float acc[4][4][4];
    #pragma unroll
    for (int mt = 0; mt < 4; ++mt)
        #pragma unroll
        for (int nt = 0; nt < 4; ++nt)
            #pragma unroll
            for (int q = 0; q < 4; ++q) acc[mt][nt][q] = 0.0f;

    #pragma unroll
    for (int ks = 0; ks < 8; ++ks) {
        const int bidx = (ks * 32 + lane) * 2;
        const uint4 h01 = __ldg(&bhp[bidx]);
        const uint4 h23 = __ldg(&bhp[bidx + 1]);
        const uint4 l01 = __ldg(&blp[bidx]);
        const uint4 l23 = __ldg(&blp[bidx + 1]);
        const uint32_t bh[4][2] = {{h01.x,h01.y},{h01.z,h01.w},{h23.x,h23.y},{h23.z,h23.w}};
        const uint32_t bl[4][2] = {{l01.x,l01.y},{l01.z,l01.w},{l23.x,l23.y},{l23.z,l23.w}};

        uint32_t ah[4][4];
        #pragma unroll
        for (int mt = 0; mt < 4; ++mt) {
            const uint32_t row = (uint32_t)(wm * 64 + mt * 16 + (lane & 15));
            const uint32_t c   = (uint32_t)(2 * ks + (lane >> 4));
            const uint32_t aoff = row * 256 + ((c ^ (row & 7)) << 4);
            asm volatile("ldmatrix.sync.aligned.m8n8.x4.shared.b16 {%0,%1,%2,%3}, [%4];"
                         : "=r"(ah[mt][0]), "=r"(ah[mt][1]), "=r"(ah[mt][2]), "=r"(ah[mt][3])
                         : "r"(sb + aoff));
        }
        #pragma unroll
        for (int mt = 0; mt < 4; ++mt)
            #pragma unroll
            for (int nt = 0; nt < 4; ++nt) {
                asm volatile(
                    "mma.sync.aligned.m16n8k16.row.col.f32.f16.f16.f32 "
                    "{%0,%1,%2,%3}, {%4,%5,%6,%7}, {%8,%9}, {%0,%1,%2,%3};"
                    : "+f"(acc[mt][nt][0]), "+f"(acc[mt][nt][1]),
                      "+f"(acc[mt][nt][2]), "+f"(acc[mt][nt][3])
                    : "r"(ah[mt][0]), "r"(ah[mt][1]), "r"(ah[mt][2]), "r"(ah[mt][3]),
                      "r"(bh[nt][0]), "r"(bh[nt][1]));
                asm volatile(
                    "mma.sync.aligned.m16n8k16.row.col.f32.f16.f16.f32 "
                    "{%0,%1,%2,%3}, {%4,%5,%6,%7}, {%8,%9}, {%0,%1,%2,%3};"
                    : "+f"(acc[mt][nt][0]), "+f"(acc[mt][nt][1]),
                      "+f"(acc[mt][nt][2]), "+f"(acc[mt][nt][3])
                    : "r"(ah[mt][0]), "r"(ah[mt][1]), "r"(ah[mt][2]), "r"(ah[mt][3]),
                      "r"(bl[nt][0]), "r"(bl[nt][1]));
            }
    }

    // --- epilogue: bias + st.v2 (c-fragment layout) ---
    const int colbase = g * 128 + (hg & 1) * 64 + wn * 32;
    #pragma unroll
    for (int nt = 0; nt < 4; ++nt) {
        const int col = colbase + nt * 8 + 2 * (lane & 3);
        const float b0 = bias[col], b1 = bias[col + 1];
        #pragma unroll
        for (int mt = 0; mt < 4; ++mt) {
            const int r0 = t0 + wm * 64 + mt * 16 + (lane >> 2);
            float2 v0 = make_float2(acc[mt][nt][0] + b0, acc[mt][nt][1] + b1);
            float2 v1 = make_float2(acc[mt][nt][2] + b0, acc[mt][nt][3] + b1);
            *(float2*)(out + (size_t)r0 * IN_F + col)       = v0;
            *(float2*)(out + (size_t)(r0 + 8) * IN_F + col) = v1;
        }
    }
}

// ---------------- launch ----------------
extern "C" void kernel_launch(void* const* d_in, const int* in_sizes, int n_in,
                              void* d_out, int out_size)
{
    const float* x    = (const float*)d_in[0];
    const int*   perm = (const int*)d_in[1];
    const float* W    = (const float*)d_in[2];
    const float* bias = (const float*)d_in[3];
    float* out = (float*)d_out;

    const int T = in_sizes[0] / IN_F;   // 16384

    convert_perm_kernel<<<1, 1024>>>(perm);
    wprep_kernel<<<64, 256>>>(W);

    cudaFuncSetAttribute(xprep_kernel,
                         cudaFuncAttributeMaxDynamicSharedMemorySize, 65536);
    xprep_kernel<<<T / 4, 256, 65536>>>(x);

    cudaFuncSetAttribute(bdl_mma_kernel,
                         cudaFuncAttributeMaxDynamicSharedMemorySize, SM_SZ);
    dim3 grid(64, T / TILE_T);          // (64 half-groups, 128 token tiles)
    bdl_mma_kernel<<<grid, 128, SM_SZ>>>(bias, out);
}

// round 11
// speedup vs baseline: 1.9418x; 1.2593x over previous
#include <cuda_runtime.h>
#include <cuda_fp16.h>
#include <cstdint>

// Problem: B=4,S=4096 -> T=16384 tokens; IN_F=OUT_F=4096; G=32; GS=GO=128.
// y[t, g*128+n] = sum_k x[t, perm[g*128+k]] * W[g,n,k] + b[g,n]
// Numerics: x -> fp16 (err ~2^-12), W -> fp16 hi + fp16 lo (err ~2^-24),
//           y = xh*Wh + xh*Wl with f32 accum  => norm rel err ~2e-4 < 1e-3.
#define IN_F   4096
#define G      32
#define TMAX   16384
#define TILE_T 128

// ---------------- device scratch (static; no allocation) ----------------
__device__ int      g_perm[IN_F];
__device__ uint32_t g_whf[64 * 4096];     // W hi fragments per half-group (fp16x2)
__device__ uint32_t g_wlf[64 * 4096];     // W lo fragments (fp16x2)
// Pre-swizzled fp16 A tiles: [ttile=128][g=32][32KB tile]
__device__ unsigned char g_xt[(size_t)128 * 32 * 32768];

__device__ __forceinline__ uint32_t smem_u32(const void* p) {
    uint32_t a;
    asm("{ .reg .u64 t; cvta.to.shared.u64 t, %1; cvt.u32.u64 %0, t; }" : "=r"(a) : "l"(p));
    return a;
}

__device__ __forceinline__ uint32_t pack_h2(float lo, float hi) {
    __half2 h = __floats2half2_rn(lo, hi);   // lo -> low 16 bits
    return *(uint32_t*)&h;
}

// ---------------- pass 0a: normalize perm (int64-or-int32 -> int32) ----------------
__global__ void convert_perm_kernel(const int* __restrict__ p32) {
    __shared__ int is64;
    if (threadIdx.x == 0) {
        int all0 = 1;
        #pragma unroll
        for (int i = 1; i < 16; i += 2) all0 &= (p32[i] == 0);
        is64 = all0;
    }
    __syncthreads();
    const int w = is64;
    for (int i = threadIdx.x; i < IN_F; i += blockDim.x)
        g_perm[i] = w ? p32[2 * i] : p32[i];
}

// ---------------- pass 0b: W -> fp16 hi/lo, gmem-LDG fragment order ----------------
// e = (((wn*8 + ks)*32 + lane)*4 + nt)*2 + r
//   n  = (hg&1)*64 + wn*32 + nt*8 + lane/4 ; k0 = ks*16 + 2*(lane&3) + r*8
__global__ void wprep_kernel(const float* __restrict__ W) {
    const int hg = blockIdx.x;            // 0..63
    const int g = hg >> 1;
    for (int e = threadIdx.x; e < 4096; e += blockDim.x) {
        const int r    = e & 1;
        const int nt   = (e >> 1) & 3;
        const int lane = (e >> 3) & 31;
        const int ks   = (e >> 8) & 7;
        const int wn   = e >> 11;
        const int n    = (hg & 1) * 64 + wn * 32 + nt * 8 + (lane >> 2);
        const int k0   = ks * 16 + 2 * (lane & 3) + r * 8;
        const float v0 = W[((size_t)g * 128 + n) * 128 + k0];
        const float v1 = W[((size_t)g * 128 + n) * 128 + k0 + 1];
        const float h0 = __half2float(__float2half_rn(v0));
        const float h1 = __half2float(__float2half_rn(v1));
        g_whf[hg * 4096 + e] = pack_h2(h0, h1);
        g_wlf[hg * 4096 + e] = pack_h2(v0 - h0, v1 - h1);
    }
}

// ---------------- pass 1: permute + fp16 convert into GEMM-ready tiles ----------------
// Block: 8 tokens, 256 threads (8 warps), 64 KB dyn smem of fp16 rows.
// Phase 1: coalesced float4 loads -> fp16 convert -> STS.64 (coalesced).
// Phase 2: half-warp covers one (token,group) output row; lane q handles
// kp=4q..4q+3: 2x LDG.128 (perm, L1-hot), 8x LDS.U16, 4 shift-ORs, 1x STG.128.
__global__ __launch_bounds__(256) void xprep_kernel(const float* __restrict__ x) {
    extern __shared__ unsigned short rows16[];      // 8 * 4096 fp16 = 64 KB
    const int t0    = blockIdx.x * 8;
    const int ttile = t0 >> 7;
    const int tbase = t0 & 127;
    const int tid = threadIdx.x, lane = tid & 31, wid = tid >> 5;

    // Phase 1: load + convert 8 rows
    {
        const float4* src = (const float4*)(x + (size_t)t0 * IN_F);
        uint2* r2 = (uint2*)rows16;
        #pragma unroll 8
        for (int i = tid; i < 8192; i += 256) {
            const float4 v = src[i];
            r2[i] = make_uint2(pack_h2(v.x, v.y), pack_h2(v.z, v.w));
        }
    }
    __syncthreads();

    // Phase 2: gather-permute into swizzled tiles
    const int q       = lane & 15;                  // 16B chunk within row
    const int half_id = wid * 2 + (lane >> 4);      // 0..15

    #pragma unroll 4
    for (int it = 0; it < 16; ++it) {
        const int rt  = it * 16 + half_id;          // 0..255
        const int tok = rt >> 5;                    // 0..7
        const int g   = rt & 31;
        const unsigned short* row = rows16 + tok * IN_F;

        const int4* pp = (const int4*)(g_perm + g * 128 + 8 * q);
        const int4 pa = pp[0];
        const int4 pb = pp[1];

        uint4 v;
        v.x = (uint32_t)row[pa.x] | ((uint32_t)row[pa.y] << 16);
        v.y = (uint32_t)row[pa.z] | ((uint32_t)row[pa.w] << 16);
        v.z = (uint32_t)row[pb.x] | ((uint32_t)row[pb.y] << 16);
        v.w = (uint32_t)row[pb.z] | ((uint32_t)row[pb.w] << 16);

        const uint32_t t   = (uint32_t)(tbase + tok);
        const uint32_t off = t * 256 + (((uint32_t)q ^ (t & 7)) << 4);
        *(uint4*)(g_xt + ((size_t)ttile * 32 + g) * 32768 + off) = v;
    }
}

// ---------------- pass 2: HMMA block-diagonal GEMM (identical to R10) ----------------
// CTA: 128 tokens x 64 outputs (half-group), 128 threads, warp grid 2x2,
// warp tile 64x32. A tile (fp16, 32 KB) via cp.async; 3 CTA/SM.
// B (W hi/lo) straight from gmem (fragment-ordered, L1/L2-hot).
#define SM_SZ 32768

__global__ __launch_bounds__(128, 3)
void bdl_mma_kernel(const float* __restrict__ bias, float* __restrict__ out)
{
    extern __shared__ char smem[];
    const uint32_t sb = smem_u32(smem);
    const int hg = blockIdx.x;
    const int g  = hg >> 1;
    const int t0 = blockIdx.y * TILE_T;
    const int tid = threadIdx.x, lane = tid & 31, wid = tid >> 5;

    // --- A: bulk cp.async of pre-swizzled fp16 tile (32 KB) ---
    {
        const unsigned char* sa = g_xt + ((size_t)blockIdx.y * 32 + g) * 32768;
        #pragma unroll 4
        for (int e = tid; e < 2048; e += 128) {
            asm volatile("cp.async.cg.shared.global [%0], [%1], 16;"
                         :: "r"(sb + e * 16), "l"(sa + e * 16));
        }
        asm volatile("cp.async.commit_group;");
        asm volatile("cp.async.wait_group 0;");
    }
    __syncthreads();

    // --- mainloop: warp grid 2(m) x 2(n); warp tile 64 tokens x 32 outputs ---
    const int wm = wid & 1;
    const int wn = wid >> 1;

    const uint4* bhp = (const uint4*)(g_whf + hg * 4096 + wn * 2048);
    const uint4* blp = (const uint4*)(g_wlf + hg * 4096 + wn * 2048);

    float acc[4][4][4];
    #pragma unroll
    for (int mt = 0; mt < 4; ++mt)
        #pragma unroll
        for (int nt = 0; nt < 4; ++nt)
            #pragma unroll
            for (int q = 0; q < 4; ++q) acc[mt][nt][q] = 0.0f;

    #pragma unroll
    for (int ks = 0; ks < 8; ++ks) {
        const int bidx = (ks * 32 + lane) * 2;
        const uint4 h01 = __ldg(&bhp[bidx]);
        const uint4 h23 = __ldg(&bhp[bidx + 1]);
        const uint4 l01 = __ldg(&blp[bidx]);
        const uint4 l23 = __ldg(&blp[bidx + 1]);
        const uint32_t bh[4][2] = {{h01.x,h01.y},{h01.z,h01.w},{h23.x,h23.y},{h23.z,h23.w}};
        const uint32_t bl[4][2] = {{l01.x,l01.y},{l01.z,l01.w},{l23.x,l23.y},{l23.z,l23.w}};

        uint32_t ah[4][4];
        #pragma unroll
        for (int mt = 0; mt < 4; ++mt) {
            const uint32_t row = (uint32_t)(wm * 64 + mt * 16 + (lane & 15));
            const uint32_t c   = (uint32_t)(2 * ks + (lane >> 4));
            const uint32_t aoff = row * 256 + ((c ^ (row & 7)) << 4);
            asm volatile("ldmatrix.sync.aligned.m8n8.x4.shared.b16 {%0,%1,%2,%3}, [%4];"
                         : "=r"(ah[mt][0]), "=r"(ah[mt][1]), "=r"(ah[mt][2]), "=r"(ah[mt][3])
                         : "r"(sb + aoff));
        }
        #pragma unroll
        for (int mt = 0; mt < 4; ++mt)
            #pragma unroll
            for (int nt = 0; nt < 4; ++nt) {
                asm volatile(
                    "mma.sync.aligned.m16n8k16.row.col.f32.f16.f16.f32 "
                    "{%0,%1,%2,%3}, {%4,%5,%6,%7}, {%8,%9}, {%0,%1,%2,%3};"
                    : "+f"(acc[mt][nt][0]), "+f"(acc[mt][nt][1]),
                      "+f"(acc[mt][nt][2]), "+f"(acc[mt][nt][3])
                    : "r"(ah[mt][0]), "r"(ah[mt][1]), "r"(ah[mt][2]), "r"(ah[mt][3]),
                      "r"(bh[nt][0]), "r"(bh[nt][1]));
                asm volatile(
                    "mma.sync.aligned.m16n8k16.row.col.f32.f16.f16.f32 "
                    "{%0,%1,%2,%3}, {%4,%5,%6,%7}, {%8,%9}, {%0,%1,%2,%3};"
                    : "+f"(acc[mt][nt][0]), "+f"(acc[mt][nt][1]),
                      "+f"(acc[mt][nt][2]), "+f"(acc[mt][nt][3])
                    : "r"(ah[mt][0]), "r"(ah[mt][1]), "r"(ah[mt][2]), "r"(ah[mt][3]),
                      "r"(bl[nt][0]), "r"(bl[nt][1]));
            }
    }

    // --- epilogue: bias + st.v2 (c-fragment layout) ---
    const int colbase = g * 128 + (hg & 1) * 64 + wn * 32;
    #pragma unroll
    for (int nt = 0; nt < 4; ++nt) {
        const int col = colbase + nt * 8 + 2 * (lane & 3);
        const float b0 = bias[col], b1 = bias[col + 1];
        #pragma unroll
        for (int mt = 0; mt < 4; ++mt) {
            const int r0 = t0 + wm * 64 + mt * 16 + (lane >> 2);
            float2 v0 = make_float2(acc[mt][nt][0] + b0, acc[mt][nt][1] + b1);
            float2 v1 = make_float2(acc[mt][nt][2] + b0, acc[mt][nt][3] + b1);
            *(float2*)(out + (size_t)r0 * IN_F + col)       = v0;
            *(float2*)(out + (size_t)(r0 + 8) * IN_F + col) = v1;
        }
    }
}

// ---------------- launch ----------------
extern "C" void kernel_launch(void* const* d_in, const int* in_sizes, int n_in,
                              void* d_out, int out_size)
{
    const float* x    = (const float*)d_in[0];
    const int*   perm = (const int*)d_in[1];
    const float* W    = (const float*)d_in[2];
    const float* bias = (const float*)d_in[3];
    float* out = (float*)d_out;

    const int T = in_sizes[0] / IN_F;   // 16384

    convert_perm_kernel<<<1, 1024>>>(perm);
    wprep_kernel<<<64, 256>>>(W);

    cudaFuncSetAttribute(xprep_kernel,
                         cudaFuncAttributeMaxDynamicSharedMemorySize, 65536);
    xprep_kernel<<<T / 8, 256, 65536>>>(x);

    cudaFuncSetAttribute(bdl_mma_kernel,
                         cudaFuncAttributeMaxDynamicSharedMemorySize, SM_SZ);
    dim3 grid(64, T / TILE_T);          // (64 half-groups, 128 token tiles)
    bdl_mma_kernel<<<grid, 128, SM_SZ>>>(bias, out);
}